// round 1
// baseline (speedup 1.0000x reference)
#include <cuda_runtime.h>
#include <math_constants.h>

#define NPTS 1024
#define DD   64
#define HA   256

// ---------------- persistent device scratch (no allocations allowed) ----------------
__device__ float g_qa[NPTS * HA];    // qa'[i][n] = (x@Wq)@aW1 + ab1 + pb2@aW1
__device__ float g_ka[NPTS * HA];    // ka[j][n]  = (x@Wk)@aW1
__device__ float g_vp[NPTS * DD];    // v'[j][d]  = x@Wv + pb2
__device__ float g_pW2a[DD * HA];    // pW2 @ aW1

// ---------------- P0: pW2a = pW2 @ aW1 ----------------
__global__ void prep_pw2a(const float* __restrict__ pW2, const float* __restrict__ aW1) {
    int k = blockIdx.x;     // 0..63
    int n = threadIdx.x;    // 0..255
    float s = 0.f;
    #pragma unroll 16
    for (int c = 0; c < 64; ++c) s = fmaf(pW2[k * 64 + c], aW1[c * 256 + n], s);
    g_pW2a[k * 256 + n] = s;
}

// ---------------- P1: projections + folded biases ----------------
__global__ void prep_qkv(const float* __restrict__ x,  const float* __restrict__ Wq,
                         const float* __restrict__ Wk, const float* __restrict__ Wv,
                         const float* __restrict__ aW1, const float* __restrict__ ab1,
                         const float* __restrict__ pb2) {
    __shared__ float sx[64], sq[64], sk[64];
    int i = blockIdx.x, t = threadIdx.x;
    if (t < 64) sx[t] = x[i * 64 + t];
    __syncthreads();
    if (t < 64) {
        float aq = 0.f, ak = 0.f, av = 0.f;
        #pragma unroll 16
        for (int c = 0; c < 64; ++c) {
            float xc = sx[c];
            aq = fmaf(xc, Wq[c * 64 + t], aq);
            ak = fmaf(xc, Wk[c * 64 + t], ak);
            av = fmaf(xc, Wv[c * 64 + t], av);
        }
        sq[t] = aq; sk[t] = ak;
        g_vp[i * 64 + t] = av + pb2[t];
    }
    __syncthreads();
    int n = t; // 0..255
    float accq = 0.f, acck = 0.f, accb = 0.f;
    #pragma unroll 8
    for (int c = 0; c < 64; ++c) {
        float w = aW1[c * 256 + n];
        accq = fmaf(sq[c], w, accq);
        acck = fmaf(sk[c], w, acck);
        accb = fmaf(pb2[c], w, accb);
    }
    g_qa[i * HA + n] = accq + ab1[n] + accb;
    g_ka[i * HA + n] = acck;
}

// ---------------- main fused kernel: one CTA per query i ----------------
// smem float offsets
#define OFF_W2A 0u        // 64*256 interleaved
#define OFF_AW2 16384u    // 256*64 interleaved
#define OFF_PW2 32768u    // 64*64 plain
#define OFF_H   36864u    // 128*68
#define OFF_SIM 45568u    // 128*68
#define OFF_QA  54272u    // 256
#define OFF_PW1 54528u    // 128
#define OFF_PB1 54656u    // 64
#define OFF_PX  54720u    // 128
#define OFF_PY  54848u    // 128
#define SMEM_FLOATS 54976u
#define SMEM_BYTES  (SMEM_FLOATS * 4u)

extern __shared__ float smem[];

__global__ __launch_bounds__(512, 1)
void pt_main(const float* __restrict__ pos, const float* __restrict__ pW1,
             const float* __restrict__ pb1, const float* __restrict__ pW2,
             const float* __restrict__ aW2, float* __restrict__ out) {
    const int i   = blockIdx.x;
    const int tid = threadIdx.x;

    float* sW2a = smem + OFF_W2A;
    float* sAW2 = smem + OFF_AW2;
    float* sPW2 = smem + OFF_PW2;
    float* sH   = smem + OFF_H;
    float* sSim = smem + OFF_SIM;
    float* sQa  = smem + OFF_QA;
    float* sPW1 = smem + OFF_PW1;
    float* sPb1 = smem + OFF_PB1;
    float* sPx  = smem + OFF_PX;
    float* sPy  = smem + OFF_PY;

    // ---- stage weights (interleaved float4 layout: elem(k, n=g*64+m) at k*256 + (m>>2)*16 + g*4 + (m&3)) ----
    for (int idx = tid; idx < 64 * 256; idx += 512) {
        int k = idx >> 8, n = idx & 255;
        int gg = n >> 6, m = n & 63;
        sW2a[k * 256 + (m >> 2) * 16 + gg * 4 + (m & 3)] = g_pW2a[idx];
    }
    // aW2: elem(n=g*64+nn, d) at nn*256 + (d>>2)*16 + g*4 + (d&3)
    for (int idx = tid; idx < 256 * 64; idx += 512) {
        int n = idx >> 6, d = idx & 63;
        int gg = n >> 6, nn = n & 63;
        sAW2[nn * 256 + (d >> 2) * 16 + gg * 4 + (d & 3)] = aW2[idx];
    }
    for (int idx = tid; idx < 64 * 64; idx += 512) sPW2[idx] = pW2[idx];
    if (tid < 128) sPW1[tid] = pW1[tid];
    if (tid < 64)  sPb1[tid] = pb1[tid];
    if (tid < 256) sQa[tid]  = g_qa[i * 256 + tid];
    const float pix = pos[i * 2 + 0];
    const float piy = pos[i * 2 + 1];

    const int j_loc = tid >> 2;   // 0..127 (phase B/C: one j per quad)
    const int g     = tid & 3;    // 0..3   (64-col slice)
    const int d_e   = tid & 63;   // phase E channel
    const int jsub  = tid >> 6;   // 0..7   (phase E j sub-range)

    float m_run = -CUDART_INF_F, l_run = 0.f, num_run = 0.f;

    for (int c = 0; c < 8; ++c) {
        const int jbase = c * 128;
        __syncthreads();                       // prev phase E done with sH/sSim
        if (tid < 128) {
            sPx[tid] = pos[(jbase + tid) * 2 + 0];
            sPy[tid] = pos[(jbase + tid) * 2 + 1];
        }
        __syncthreads();

        // ---- Phase A: H[j][k] = relu(dx*pW1[0,k] + dy*pW1[1,k] + pb1[k]) ----
        for (int idx = tid; idx < 128 * 64; idx += 512) {
            int j = idx >> 6, k = idx & 63;
            float dx = pix - sPx[j];
            float dy = piy - sPy[j];
            float h = fmaxf(fmaf(dx, sPW1[k], fmaf(dy, sPW1[64 + k], sPb1[k])), 0.f);
            sH[j * 68 + k] = h;
        }
        __syncthreads();

        // ---- Phase B: preact[64] = qa'[i] - ka[j] + H[j]@pW2a (this thread's 64-col slice) ----
        float acc[64];
        {
            const float4* kap = reinterpret_cast<const float4*>(g_ka + (size_t)(jbase + j_loc) * 256 + g * 64);
            const float4* qap = reinterpret_cast<const float4*>(sQa + g * 64);
            #pragma unroll
            for (int mq = 0; mq < 16; ++mq) {
                float4 kv = kap[mq], qv = qap[mq];
                acc[4 * mq + 0] = qv.x - kv.x;
                acc[4 * mq + 1] = qv.y - kv.y;
                acc[4 * mq + 2] = qv.z - kv.z;
                acc[4 * mq + 3] = qv.w - kv.w;
            }
        }
        {
            const float*  hrow = sH + j_loc * 68;
            const float4* wb   = reinterpret_cast<const float4*>(sW2a + g * 4);
            #pragma unroll 2
            for (int k = 0; k < 64; ++k) {
                float hk = hrow[k];
                const float4* w4 = wb + k * 64;      // float4 index: k*256 floats
                #pragma unroll
                for (int mq = 0; mq < 16; ++mq) {
                    float4 w = w4[mq * 4];           // +16 floats per mq
                    acc[4 * mq + 0] = fmaf(hk, w.x, acc[4 * mq + 0]);
                    acc[4 * mq + 1] = fmaf(hk, w.y, acc[4 * mq + 1]);
                    acc[4 * mq + 2] = fmaf(hk, w.z, acc[4 * mq + 2]);
                    acc[4 * mq + 3] = fmaf(hk, w.w, acc[4 * mq + 3]);
                }
            }
        }
        #pragma unroll
        for (int m = 0; m < 64; ++m) acc[m] = fmaxf(acc[m], 0.f);   // hidden

        // ---- Phase C: sim[j][d] partial = hidden_slice @ aW2, quad-reduced ----
        #pragma unroll
        for (int p = 0; p < 2; ++p) {
            float ps[32];
            #pragma unroll
            for (int z = 0; z < 32; ++z) ps[z] = 0.f;
            const float4* ab = reinterpret_cast<const float4*>(sAW2 + g * 4 + p * 128);
            #pragma unroll 2
            for (int nn = 0; nn < 64; ++nn) {
                float hv = acc[nn];
                const float4* w4 = ab + nn * 64;
                #pragma unroll
                for (int dq = 0; dq < 8; ++dq) {
                    float4 w = w4[dq * 4];
                    ps[4 * dq + 0] = fmaf(hv, w.x, ps[4 * dq + 0]);
                    ps[4 * dq + 1] = fmaf(hv, w.y, ps[4 * dq + 1]);
                    ps[4 * dq + 2] = fmaf(hv, w.z, ps[4 * dq + 2]);
                    ps[4 * dq + 3] = fmaf(hv, w.w, ps[4 * dq + 3]);
                }
            }
            #pragma unroll
            for (int z = 0; z < 32; ++z) {
                ps[z] += __shfl_xor_sync(0xffffffffu, ps[z], 1);
                ps[z] += __shfl_xor_sync(0xffffffffu, ps[z], 2);
            }
            if (g == p) {
                float4* so = reinterpret_cast<float4*>(sSim + j_loc * 68 + p * 32);
                #pragma unroll
                for (int dq = 0; dq < 8; ++dq)
                    so[dq] = make_float4(ps[4 * dq], ps[4 * dq + 1], ps[4 * dq + 2], ps[4 * dq + 3]);
            }
        }
        __syncthreads();

        // ---- Phase E: rpe recompute + channel-wise online softmax + aggregation ----
        float r[16];
        #pragma unroll
        for (int jj = 0; jj < 16; ++jj) r[jj] = 0.f;
        const float* hbase = sH + (jsub * 16) * 68;
        #pragma unroll 4
        for (int k = 0; k < 64; ++k) {
            float wvk = sPW2[k * 64 + d_e];
            #pragma unroll
            for (int jj = 0; jj < 16; ++jj)
                r[jj] = fmaf(hbase[jj * 68 + k], wvk, r[jj]);
        }
        #pragma unroll
        for (int jj = 0; jj < 16; ++jj) {
            int j = jsub * 16 + jj;
            float s  = sSim[j * 68 + d_e];
            float vv = g_vp[(size_t)(jbase + j) * 64 + d_e] + r[jj];
            float mn = fmaxf(m_run, s);
            float cs = __expf(m_run - mn);
            float pe = __expf(s - mn);
            l_run   = fmaf(l_run, cs, pe);
            num_run = fmaf(num_run, cs, pe * vv);
            m_run   = mn;
        }
    }

    // ---- final cross-jsub merge (reuse sH as scratch) ----
    __syncthreads();
    float* sRed = sH;
    sRed[jsub * 64 + d_e]        = m_run;
    sRed[512 + jsub * 64 + d_e]  = l_run;
    sRed[1024 + jsub * 64 + d_e] = num_run;
    __syncthreads();
    if (tid < 64) {
        float M = -CUDART_INF_F;
        #pragma unroll
        for (int s2 = 0; s2 < 8; ++s2) M = fmaxf(M, sRed[s2 * 64 + tid]);
        float L = 0.f, NU = 0.f;
        #pragma unroll
        for (int s2 = 0; s2 < 8; ++s2) {
            float e = __expf(sRed[s2 * 64 + tid] - M);
            L  = fmaf(sRed[512 + s2 * 64 + tid], e, L);
            NU = fmaf(sRed[1024 + s2 * 64 + tid], e, NU);
        }
        out[i * 64 + tid] = NU / L;
    }
}

// ---------------- launch ----------------
extern "C" void kernel_launch(void* const* d_in, const int* in_sizes, int n_in,
                              void* d_out, int out_size) {
    const float* x   = (const float*)d_in[0];
    const float* pos = (const float*)d_in[1];
    const float* Wq  = (const float*)d_in[2];
    const float* Wk  = (const float*)d_in[3];
    const float* Wv  = (const float*)d_in[4];
    const float* pW1 = (const float*)d_in[5];
    const float* pb1 = (const float*)d_in[6];
    const float* pW2 = (const float*)d_in[7];
    const float* pb2 = (const float*)d_in[8];
    const float* aW1 = (const float*)d_in[9];
    const float* ab1 = (const float*)d_in[10];
    const float* aW2 = (const float*)d_in[11];
    // d_in[12] = ab2: constant over j per channel -> cancels in softmax (exact), unused.
    float* out = (float*)d_out;

    cudaFuncSetAttribute(pt_main, cudaFuncAttributeMaxDynamicSharedMemorySize, SMEM_BYTES);

    prep_pw2a<<<64, 256>>>(pW2, aW1);
    prep_qkv<<<NPTS, 256>>>(x, Wq, Wk, Wv, aW1, ab1, pb2);
    pt_main<<<NPTS, 512, SMEM_BYTES>>>(pos, pW1, pb1, pW2, aW2, out);
}

// round 3
// speedup vs baseline: 3.1707x; 3.1707x over previous
#include <cuda_runtime.h>
#include <math_constants.h>

#define NPTS 1024
#define HA   256

// ---------------- persistent device scratch ----------------
__device__ float g_qa[NPTS * HA];    // qa'[i][n] = (x@Wq)@aW1 + ab1 + pb2@aW1
__device__ float g_ka[NPTS * HA];    // ka[j][n]  = (x@Wk)@aW1
__device__ float g_vp[NPTS * 64];    // v'[j][d]  = x@Wv + pb2
__device__ float g_pW2a[64 * HA];    // pW2 @ aW1

// ---------------- f32x2 helpers (FFMA2 — PTX-only on sm_103a) ----------------
__device__ __forceinline__ unsigned long long ffma2(unsigned long long a, unsigned long long b, unsigned long long c) {
    unsigned long long d;
    asm("fma.rn.f32x2 %0, %1, %2, %3;" : "=l"(d) : "l"(a), "l"(b), "l"(c));
    return d;
}
__device__ __forceinline__ unsigned long long pack2(float lo, float hi) {
    unsigned long long r;
    asm("mov.b64 %0, {%1, %2};" : "=l"(r) : "f"(lo), "f"(hi));
    return r;
}
__device__ __forceinline__ void unpack2(unsigned long long v, float& lo, float& hi) {
    asm("mov.b64 {%0, %1}, %2;" : "=f"(lo), "=f"(hi) : "l"(v));
}

// ---------------- P0: pW2a = pW2 @ aW1 ----------------
__global__ void prep_pw2a(const float* __restrict__ pW2, const float* __restrict__ aW1) {
    int k = blockIdx.x;     // 0..63
    int n = threadIdx.x;    // 0..255
    float s = 0.f;
    #pragma unroll 16
    for (int c = 0; c < 64; ++c) s = fmaf(pW2[k * 64 + c], aW1[c * 256 + n], s);
    g_pW2a[k * 256 + n] = s;
}

// ---------------- P1: projections + folded biases ----------------
__global__ void prep_qkv(const float* __restrict__ x,  const float* __restrict__ Wq,
                         const float* __restrict__ Wk, const float* __restrict__ Wv,
                         const float* __restrict__ aW1, const float* __restrict__ ab1,
                         const float* __restrict__ pb2) {
    __shared__ float sx[64], sq[64], sk[64];
    int i = blockIdx.x, t = threadIdx.x;
    if (t < 64) sx[t] = x[i * 64 + t];
    __syncthreads();
    if (t < 64) {
        float aq = 0.f, ak = 0.f, av = 0.f;
        #pragma unroll 16
        for (int c = 0; c < 64; ++c) {
            float xc = sx[c];
            aq = fmaf(xc, Wq[c * 64 + t], aq);
            ak = fmaf(xc, Wk[c * 64 + t], ak);
            av = fmaf(xc, Wv[c * 64 + t], av);
        }
        sq[t] = aq; sk[t] = ak;
        g_vp[i * 64 + t] = av + pb2[t];
    }
    __syncthreads();
    int n = t; // 0..255
    float accq = 0.f, acck = 0.f, accb = 0.f;
    #pragma unroll 8
    for (int c = 0; c < 64; ++c) {
        float w = aW1[c * 256 + n];
        accq = fmaf(sq[c], w, accq);
        acck = fmaf(sk[c], w, acck);
        accb = fmaf(pb2[c], w, accb);
    }
    g_qa[i * HA + n] = accq + ab1[n] + accb;
    g_ka[i * HA + n] = acck;
}

// ---------------- main fused kernel: one CTA per query i ----------------
// smem float offsets
#define OFF_W2A 0u        // 64 x 256 row-major
#define OFF_AW2 16384u    // 256 x 64 row-major
#define OFF_PW2 32768u    // 64 x 64 row-major
#define OFF_H   36864u    // 64k x 68j  (k-major!)
#define OFF_HID 41216u    // 64j x 256n (also hosts sim partials A/B in first 8192 floats)
#define OFF_PW1 57600u    // 128
#define OFF_PB1 57728u    // 64
#define SMEM_FLOATS 57792u
#define SMEM_BYTES  (SMEM_FLOATS * 4u)   // 231168 B

extern __shared__ float smem[];

__global__ __launch_bounds__(512, 1)
void pt_main(const float* __restrict__ pos, const float* __restrict__ pW1,
             const float* __restrict__ pb1, const float* __restrict__ pW2,
             const float* __restrict__ aW2, float* __restrict__ out) {
    const int i   = blockIdx.x;
    const int tid = threadIdx.x;

    float* sW2a = smem + OFF_W2A;
    float* sAW2 = smem + OFF_AW2;
    float* sPW2 = smem + OFF_PW2;
    float* sH   = smem + OFF_H;
    float* sHid = smem + OFF_HID;
    float* sPW1 = smem + OFF_PW1;
    float* sPb1 = smem + OFF_PB1;

    // ---- stage weights (plain row-major) ----
    for (int idx = tid; idx < 64 * 256; idx += 512) sW2a[idx] = g_pW2a[idx];
    for (int idx = tid; idx < 256 * 64; idx += 512) sAW2[idx] = aW2[idx];
    for (int idx = tid; idx < 64 * 64;  idx += 512) sPW2[idx] = pW2[idx];
    if (tid < 128) sPW1[tid] = pW1[tid];
    if (tid < 64)  sPb1[tid] = pb1[tid];

    const float pix = __ldg(pos + i * 2 + 0);
    const float piy = __ldg(pos + i * 2 + 1);

    // phase mappings
    const int jA   = tid & 63;             // phase A: j index
    const int kA0  = tid >> 6;             // phase A: k sub
    const int j0B  = (tid >> 4) * 2;       // phase B: 2 j rows (0..62)
    const int cbB  = (tid & 15) * 4;       // phase B: col base; cols cb+g*64
    const int segC = tid >> 8;             // phase C: K-half
    const int j0C  = ((tid >> 4) & 15) * 4;// phase C: 4 j rows
    const int d4C  = (tid & 15) * 4;       // phase C: 4 d cols
    const int d_e  = tid & 63;             // phase E: channel
    const int jsub = tid >> 6;             // phase E: 8-j group
    const int j0E  = jsub * 8;

    float m_run = -CUDART_INF_F, l_run = 0.f, num_run = 0.f;

    for (int c = 0; c < 16; ++c) {
        const int jbase = c * 64;
        __syncthreads();   // S1: prev phase E done with sH/sHid; (chunk0: staging done)

        // ---- Phase A: H[k][j] = relu(dx*pW1[0,k] + dy*pW1[1,k] + pb1[k]), k-major ----
        {
            float2 pj = *reinterpret_cast<const float2*>(pos + (jbase + jA) * 2);
            float dx = pix - pj.x, dy = piy - pj.y;
            #pragma unroll
            for (int p = 0; p < 8; ++p) {
                int k = p * 8 + kA0;
                float h = fmaxf(fmaf(dx, sPW1[k], fmaf(dy, sPW1[64 + k], sPb1[k])), 0.f);
                sH[k * 68 + jA] = h;
            }
        }
        __syncthreads();   // S2: H ready

        // ---- Phase B: hidden[64j][256n] = relu(qa - ka + H@pW2a), Mr=2 Nr=16 f32x2 ----
        {
            unsigned long long accB[16];
            #pragma unroll
            for (int z = 0; z < 16; ++z) accB[z] = 0ull;

            #pragma unroll 4
            for (int k = 0; k < 64; ++k) {
                float2 hv = *reinterpret_cast<const float2*>(sH + k * 68 + j0B);
                unsigned long long hp0 = pack2(hv.x, hv.x);
                unsigned long long hp1 = pack2(hv.y, hv.y);
                const float* wr = sW2a + k * 256 + cbB;
                #pragma unroll
                for (int g = 0; g < 4; ++g) {
                    ulonglong2 w = *reinterpret_cast<const ulonglong2*>(wr + g * 64);
                    accB[g * 2 + 0]     = ffma2(hp0, w.x, accB[g * 2 + 0]);
                    accB[g * 2 + 1]     = ffma2(hp0, w.y, accB[g * 2 + 1]);
                    accB[8 + g * 2 + 0] = ffma2(hp1, w.x, accB[8 + g * 2 + 0]);
                    accB[8 + g * 2 + 1] = ffma2(hp1, w.y, accB[8 + g * 2 + 1]);
                }
            }
            // epilogue: + qa - ka, relu, store
            #pragma unroll
            for (int j = 0; j < 2; ++j) {
                const int gj = jbase + j0B + j;
                #pragma unroll
                for (int g = 0; g < 4; ++g) {
                    int col = cbB + g * 64;
                    float4 qa4 = __ldg(reinterpret_cast<const float4*>(g_qa + i * 256 + col));
                    float4 ka4 = __ldg(reinterpret_cast<const float4*>(g_ka + (size_t)gj * 256 + col));
                    float a0, a1, a2, a3;
                    unpack2(accB[j * 8 + g * 2 + 0], a0, a1);
                    unpack2(accB[j * 8 + g * 2 + 1], a2, a3);
                    float4 o;
                    o.x = fmaxf(a0 + qa4.x - ka4.x, 0.f);
                    o.y = fmaxf(a1 + qa4.y - ka4.y, 0.f);
                    o.z = fmaxf(a2 + qa4.z - ka4.z, 0.f);
                    o.w = fmaxf(a3 + qa4.w - ka4.w, 0.f);
                    *reinterpret_cast<float4*>(sHid + (j0B + j) * 256 + col) = o;
                }
            }
        }
        __syncthreads();   // S3: hidden ready

        // ---- Phase C: sim[64j][64d] = hidden @ aW2, K split in 2 segs, Mr=4 Nr=4 f32x2 ----
        unsigned long long accC[8];
        {
            #pragma unroll
            for (int z = 0; z < 8; ++z) accC[z] = 0ull;
            const int nb = segC * 128;
            #pragma unroll 4
            for (int nn = 0; nn < 128; ++nn) {
                int n = nb + nn;
                const float* hc = sHid + j0C * 256 + n;
                unsigned long long hp0 = pack2(hc[0],   hc[0]);
                unsigned long long hp1 = pack2(hc[256], hc[256]);
                unsigned long long hp2 = pack2(hc[512], hc[512]);
                unsigned long long hp3 = pack2(hc[768], hc[768]);
                ulonglong2 w = *reinterpret_cast<const ulonglong2*>(sAW2 + n * 64 + d4C);
                accC[0] = ffma2(hp0, w.x, accC[0]);  accC[1] = ffma2(hp0, w.y, accC[1]);
                accC[2] = ffma2(hp1, w.x, accC[2]);  accC[3] = ffma2(hp1, w.y, accC[3]);
                accC[4] = ffma2(hp2, w.x, accC[4]);  accC[5] = ffma2(hp2, w.y, accC[5]);
                accC[6] = ffma2(hp3, w.x, accC[6]);  accC[7] = ffma2(hp3, w.y, accC[7]);
            }
        }
        __syncthreads();   // S4: all hidden reads done — safe to overwrite with partials

        // write sim partials: seg0 -> sHid[0..4095], seg1 -> sHid[4096..8191]
        {
            float* sPart = sHid + segC * 4096;
            #pragma unroll
            for (int jj = 0; jj < 4; ++jj) {
                ulonglong2 t;
                t.x = accC[jj * 2 + 0];
                t.y = accC[jj * 2 + 1];
                *reinterpret_cast<ulonglong2*>(sPart + (j0C + jj) * 64 + d4C) = t;
            }
        }
        __syncthreads();   // S5: partials ready

        // ---- Phase E: rpe recompute (f32x2) + channel-wise online softmax + aggregation ----
        {
            unsigned long long r2[4] = {0ull, 0ull, 0ull, 0ull};
            #pragma unroll 4
            for (int k = 0; k < 64; ++k) {
                float wv = sPW2[k * 64 + d_e];
                unsigned long long wp = pack2(wv, wv);
                const ulonglong2* hp = reinterpret_cast<const ulonglong2*>(sH + k * 68 + j0E);
                ulonglong2 ha = hp[0], hb = hp[1];
                r2[0] = ffma2(wp, ha.x, r2[0]);
                r2[1] = ffma2(wp, ha.y, r2[1]);
                r2[2] = ffma2(wp, hb.x, r2[2]);
                r2[3] = ffma2(wp, hb.y, r2[3]);
            }
            float rv[8];
            #pragma unroll
            for (int q = 0; q < 4; ++q) unpack2(r2[q], rv[q * 2], rv[q * 2 + 1]);
            #pragma unroll
            for (int jj = 0; jj < 8; ++jj) {
                int j = j0E + jj;
                float s  = sHid[j * 64 + d_e] + sHid[4096 + j * 64 + d_e];
                float vv = __ldg(g_vp + (size_t)(jbase + j) * 64 + d_e) + rv[jj];
                float mn = fmaxf(m_run, s);
                float cs = __expf(m_run - mn);
                float pe = __expf(s - mn);
                l_run   = fmaf(l_run, cs, pe);
                num_run = fmaf(num_run, cs, pe * vv);
                m_run   = mn;
            }
        }
    }

    // ---- final cross-jsub merge (reuse sH as scratch) ----
    __syncthreads();
    float* sRed = sH;
    sRed[jsub * 64 + d_e]        = m_run;
    sRed[512 + jsub * 64 + d_e]  = l_run;
    sRed[1024 + jsub * 64 + d_e] = num_run;
    __syncthreads();
    if (tid < 64) {
        float M = -CUDART_INF_F;
        #pragma unroll
        for (int s2 = 0; s2 < 8; ++s2) M = fmaxf(M, sRed[s2 * 64 + tid]);
        float L = 0.f, NU = 0.f;
        #pragma unroll
        for (int s2 = 0; s2 < 8; ++s2) {
            float e = __expf(sRed[s2 * 64 + tid] - M);
            L  = fmaf(sRed[512 + s2 * 64 + tid], e, L);
            NU = fmaf(sRed[1024 + s2 * 64 + tid], e, NU);
        }
        out[i * 64 + tid] = NU / L;
    }
}

// ---------------- launch ----------------
extern "C" void kernel_launch(void* const* d_in, const int* in_sizes, int n_in,
                              void* d_out, int out_size) {
    const float* x   = (const float*)d_in[0];
    const float* pos = (const float*)d_in[1];
    const float* Wq  = (const float*)d_in[2];
    const float* Wk  = (const float*)d_in[3];
    const float* Wv  = (const float*)d_in[4];
    const float* pW1 = (const float*)d_in[5];
    const float* pb1 = (const float*)d_in[6];
    const float* pW2 = (const float*)d_in[7];
    const float* pb2 = (const float*)d_in[8];
    const float* aW1 = (const float*)d_in[9];
    const float* ab1 = (const float*)d_in[10];
    const float* aW2 = (const float*)d_in[11];
    // d_in[12] = ab2: constant over j per channel -> cancels in softmax (exact), unused.
    float* out = (float*)d_out;

    cudaFuncSetAttribute(pt_main, cudaFuncAttributeMaxDynamicSharedMemorySize, SMEM_BYTES);

    prep_pw2a<<<64, 256>>>(pW2, aW1);
    prep_qkv<<<NPTS, 256>>>(x, Wq, Wk, Wv, aW1, ab1, pb2);
    pt_main<<<NPTS, 512, SMEM_BYTES>>>(pos, pW1, pb1, pW2, aW2, out);
}